// round 6
// baseline (speedup 1.0000x reference)
#include <cuda_runtime.h>
#include <cuda_bf16.h>
#include <math.h>
#include <cstdint>

#define NQ       12
#define NLAYERS  5
#define DIM      4096
#define BSZ      4096

// ---------------- device scratch (no allocations allowed) ----------------
__device__ float2 g_psi0[DIM];
// e4m3 3-way split operands at common scale 16x. Each element of g_h/m/l is a
// packed (re, im) fp8 pair; K dim thus interleaves re/im. Imag-operand
// C = (-im, re) is derived in-register inside the GEMM.
__device__ __align__(128) unsigned short g_h[(size_t)BSZ * DIM];
__device__ __align__(128) unsigned short g_m[(size_t)BSZ * DIM];
__device__ __align__(128) unsigned short g_l[(size_t)BSZ * DIM];

__device__ __forceinline__ float2 cmul(float2 a, float2 b) {
    return make_float2(a.x * b.x - a.y * b.y, a.x * b.y + a.y * b.x);
}
__device__ __forceinline__ float2 cadd(float2 a, float2 b) {
    return make_float2(a.x + b.x, a.y + b.y);
}

// fp8 pack/unpack: byte0 = lo arg, byte1 = hi arg
__device__ __forceinline__ unsigned short pack_e4m3(float lo, float hi) {
    unsigned short r;
    asm("cvt.rn.satfinite.e4m3x2.f32 %0, %1, %2;" : "=h"(r) : "f"(hi), "f"(lo));
    return r;
}
__device__ __forceinline__ float2 unpack_e4m3(unsigned short v) {
    unsigned int h2;
    asm("cvt.rn.f16x2.e4m3x2 %0, %1;" : "=r"(h2) : "h"(v));
    __half2 hh = *reinterpret_cast<__half2*>(&h2);
    return __half22float2(hh);
}

// Reference einsum 'st,blsr->bltr' applies U^T. T = U^T.
__device__ __forceinline__ void make_UT(float ph, float th, float lm,
                                        float2& T00, float2& T01,
                                        float2& T10, float2& T11) {
    float ct = cosf(0.5f * th), st = sinf(0.5f * th);
    float ap = 0.5f * (lm + ph), am = 0.5f * (lm - ph);
    float cap = cosf(ap), sap = sinf(ap);
    float cam = cosf(am), sam = sinf(am);
    float2 U00 = make_float2( ct * cap, -ct * sap);
    float2 U01 = make_float2(-st * cam,  st * sam);
    float2 U10 = make_float2( st * cam,  st * sam);
    float2 U11 = make_float2( ct * cap,  ct * sap);
    T00 = U00; T01 = U10; T10 = U01; T11 = U11;
}

// ---------------- Kernel A: data-independent prefix (layers 0..3) --------
__global__ void k_psi0(const float* __restrict__ params) {
    __shared__ float2 st[DIM];
    int tid = threadIdx.x, nt = blockDim.x;  // nt = 1024
    for (int i = tid; i < DIM; i += nt)
        st[i] = make_float2(i == 0 ? 1.0f : 0.0f, 0.0f);
    __syncthreads();

    for (int l = 0; l < NLAYERS - 1; l++) {
        for (int q = 0; q < NQ; q++) {
            const float* p = params + (l * NQ + q) * 3;
            float2 T00, T01, T10, T11;
            make_UT(p[0], p[1], p[2], T00, T01, T10, T11);
            int mask = 1 << (NQ - 1 - q);
            for (int pi = tid; pi < DIM / 2; pi += nt) {
                int low = pi & (mask - 1);
                int hi  = (pi & ~(mask - 1)) << 1;
                int i0 = hi | low, i1 = i0 | mask;
                float2 s0 = st[i0], s1 = st[i1];
                st[i0] = cadd(cmul(T00, s0), cmul(T01, s1));
                st[i1] = cadd(cmul(T10, s0), cmul(T11, s1));
            }
            __syncthreads();
        }
        // composed CNOT permutation, single sweep
        {
            float2 tmp[4];
#pragma unroll
            for (int u = 0; u < 4; u++) {
                int idx = u * 1024 + tid;
                int j = idx;
#pragma unroll
                for (int q = NQ - 2; q >= 0; q--) {
                    int cb = 1 << (NQ - 1 - q);
                    int tb = 1 << (NQ - 2 - q);
                    if (j & cb) j ^= tb;
                }
                tmp[u] = st[j];
            }
            __syncthreads();
#pragma unroll
            for (int u = 0; u < 4; u++)
                st[u * 1024 + tid] = tmp[u];
            __syncthreads();
        }
    }
    for (int i = tid; i < DIM; i += nt) g_psi0[i] = st[i];
}

// ---------------- Kernel B: per-sample layer-4 gates + fp8 split --------
__global__ void k_states(const float* __restrict__ X,
                         const float* __restrict__ params) {
    __shared__ float2 st[DIM];
    int i = blockIdx.x, tid = threadIdx.x, nt = blockDim.x;
    for (int k = tid; k < DIM; k += nt) st[k] = g_psi0[k];
    __syncthreads();

    for (int q = 0; q < NQ; q++) {
        const float* p = params + ((NLAYERS - 1) * NQ + q) * 3;
        float2 T00, T01, T10, T11;
        make_UT(p[0], p[1], p[2], T00, T01, T10, T11);
        float x = X[i * NQ + q];
        float gc = cosf(0.5f * x), gs = sinf(0.5f * x);
        // V = G^T * T
        float2 V00 = make_float2(gc * T00.x + gs * T10.x, gc * T00.y + gs * T10.y);
        float2 V01 = make_float2(gc * T01.x + gs * T11.x, gc * T01.y + gs * T11.y);
        float2 V10 = make_float2(-gs * T00.x + gc * T10.x, -gs * T00.y + gc * T10.y);
        float2 V11 = make_float2(-gs * T01.x + gc * T11.x, -gs * T01.y + gc * T11.y);

        int mask = 1 << (NQ - 1 - q);
        for (int pi = tid; pi < DIM / 2; pi += nt) {
            int low = pi & (mask - 1);
            int hi  = (pi & ~(mask - 1)) << 1;
            int i0 = hi | low, i1 = i0 | mask;
            float2 s0 = st[i0], s1 = st[i1];
            st[i0] = cadd(cmul(V00, s0), cmul(V01, s1));
            st[i1] = cadd(cmul(V10, s0), cmul(V11, s1));
        }
        __syncthreads();
    }

    size_t rowoff = (size_t)i * DIM;
    for (int k = tid; k < DIM; k += nt) {
        float re = 16.0f * st[k].x, im = 16.0f * st[k].y;
        unsigned short h = pack_e4m3(re, im);
        float2 hf = unpack_e4m3(h);
        float r1r = re - hf.x, r1i = im - hf.y;
        unsigned short m = pack_e4m3(r1r, r1i);
        float2 mf = unpack_e4m3(m);
        unsigned short l = pack_e4m3(r1r - mf.x, r1i - mf.y);
        g_h[rowoff + k] = h;
        g_m[rowoff + k] = m;
        g_l[rowoff + k] = l;
    }
}

// =============  Kernel C: fp8 m16n8k32 split Gram  ========================
// scale: operands are 16x. acc units = 256 * (true products).
// re: hh + hm + mh + hl + lh + mm   (6 chains, one shared fp32 acc)
// im: hh' + hm' + mh'               (3 chains; B' = (-im,re) derived)
// K_out = (re/256)^2 + (im/256)^2.  Triangular 128x128 tiles.
#define KROWB     8192                  // bytes per operand row (4096 cplx * 2 fp8)
#define NKT       64                    // 8192 / 128B chunks
#define TILE_B    16384                 // 128 rows x 128 bytes
#define STAGE_B   (6 * TILE_B)          // h_i,m_i,l_i,h_j,m_j,l_j = 96KB
#define NSTAGE    2
#define GRAM_SMEM (NSTAGE * STAGE_B)    // 192KB
#define GRAM_THREADS 256
#define NTILE (DIM / 128)               // 32
#define NBLK  (NTILE * (NTILE + 1) / 2) // 528

__device__ __forceinline__ uint32_t smem_u32(const void* p) {
    return (uint32_t)__cvta_generic_to_shared(p);
}
__device__ __forceinline__ void cp_async16(uint32_t dst, const void* src) {
    asm volatile("cp.async.cg.shared.global [%0], [%1], 16;" :: "r"(dst), "l"(src));
}
#define CP_COMMIT()  asm volatile("cp.async.commit_group;" ::: "memory")
#define CP_WAIT1()   asm volatile("cp.async.wait_group 1;" ::: "memory")
#define CP_WAIT0()   asm volatile("cp.async.wait_group 0;" ::: "memory")

__device__ __forceinline__ void ldsm4(uint32_t* r, uint32_t addr) {
    asm volatile("ldmatrix.sync.aligned.m8n8.x4.shared.b16 {%0,%1,%2,%3}, [%4];"
        : "=r"(r[0]), "=r"(r[1]), "=r"(r[2]), "=r"(r[3]) : "r"(addr));
}
__device__ __forceinline__ void mma_fp8(float* c, const uint32_t* a,
                                        uint32_t b0, uint32_t b1) {
    asm volatile(
        "mma.sync.aligned.m16n8k32.row.col.f32.e4m3.e4m3.f32 "
        "{%0,%1,%2,%3}, {%4,%5,%6,%7}, {%8,%9}, {%0,%1,%2,%3};"
        : "+f"(c[0]), "+f"(c[1]), "+f"(c[2]), "+f"(c[3])
        : "r"(a[0]), "r"(a[1]), "r"(a[2]), "r"(a[3]), "r"(b0), "r"(b1));
}
// bytes (re0,im0,re1,im1) -> (-im0,re0,-im1,re1): swap byte pairs + flip
// e4m3 sign bit (MSB) of bytes 0 and 2.
__device__ __forceinline__ uint32_t derive_c8(uint32_t b) {
    return __byte_perm(b, b, 0x2301) ^ 0x00800080u;
}

__global__ void __launch_bounds__(GRAM_THREADS, 1)
k_gram_mma(float* __restrict__ K) {
    extern __shared__ __align__(1024) char smem[];
    const uint32_t smem_base = smem_u32(smem);
    const int tid  = threadIdx.x;
    const int wid  = tid >> 5;
    const int lane = tid & 31;
    const int wm = wid >> 2;            // 0..1  (64-row slab)
    const int wn = wid & 3;             // 0..3  (32-col slab)

    // triangular tile mapping (bi <= bj)
    int t = blockIdx.x;
    int bj = (int)((sqrtf(8.0f * (float)t + 1.0f) - 1.0f) * 0.5f);
    while ((bj + 1) * (bj + 2) / 2 <= t) bj++;
    while (bj * (bj + 1) / 2 > t) bj--;
    int bi = t - bj * (bj + 1) / 2;

    const char* gsrc[6];
    gsrc[0] = (const char*)g_h + (size_t)bi * 128 * KROWB;
    gsrc[1] = (const char*)g_m + (size_t)bi * 128 * KROWB;
    gsrc[2] = (const char*)g_l + (size_t)bi * 128 * KROWB;
    gsrc[3] = (const char*)g_h + (size_t)bj * 128 * KROWB;
    gsrc[4] = (const char*)g_m + (size_t)bj * 128 * KROWB;
    gsrc[5] = (const char*)g_l + (size_t)bj * 128 * KROWB;

    // ldmatrix per-thread geometry (byte-based, same as bf16 version)
    const int mat = lane >> 3, rl = lane & 7;
    const int rowA_base = wm * 64 + (mat & 1) * 8 + rl;   // + mt*16
    const uint32_t kselA = (uint32_t)((mat >> 1) * 16);
    const uint32_t xA = (uint32_t)(rowA_base & 7) << 4;
    const int rowB_base = wn * 32 + (mat >> 1) * 8 + rl;  // + np*16
    const uint32_t kselB = (uint32_t)((mat & 1) * 16);
    const uint32_t xB = (uint32_t)(rowB_base & 7) << 4;

    float acc[2][4][4][4];
#pragma unroll
    for (int e = 0; e < 2; e++)
#pragma unroll
        for (int mt = 0; mt < 4; mt++)
#pragma unroll
            for (int nt = 0; nt < 4; nt++)
#pragma unroll
                for (int r = 0; r < 4; r++) acc[e][mt][nt][r] = 0.f;

    // ---------------- prologue: fill 2 stages --------------------------
#pragma unroll 1
    for (int pk = 0; pk < NSTAGE; pk++) {
        uint32_t sb = smem_base + pk * STAGE_B;
#pragma unroll
        for (int tt = 0; tt < 6; tt++) {
#pragma unroll
            for (int u = 0; u < 4; u++) {
                int p = u * 256 + tid;
                int rr = p >> 3, cc = p & 7;
                uint32_t dst = sb + tt * TILE_B + (uint32_t)rr * 128 +
                               (((uint32_t)cc * 16) ^ (((uint32_t)rr & 7) << 4));
                cp_async16(dst, gsrc[tt] + (size_t)rr * KROWB + pk * 128 + cc * 16);
            }
        }
        CP_COMMIT();
    }

    // ---------------- main loop ----------------------------------------
#pragma unroll 1
    for (int kt = 0; kt < NKT; kt++) {
        CP_WAIT1();
        __syncthreads();

        uint32_t sb = smem_base + (kt & 1) * STAGE_B;
        uint32_t aH = sb + (uint32_t)rowA_base * 128;
        uint32_t aM = aH + TILE_B;
        uint32_t aL = aM + TILE_B;
        uint32_t bH = sb + 3 * TILE_B + (uint32_t)rowB_base * 128;
        uint32_t bM = bH + TILE_B;
        uint32_t bL = bM + TILE_B;

#pragma unroll
        for (int ks = 0; ks < 4; ks++) {      // each ks = k32 fp8 = 16 complex
            uint32_t cA = ((uint32_t)(ks * 32) + kselA) ^ xA;
            uint32_t cB = ((uint32_t)(ks * 32) + kselB) ^ xB;

            uint32_t ah[4][4], am[4][4], al[4][4];
#pragma unroll
            for (int mt = 0; mt < 4; mt++) {
                ldsm4(ah[mt], aH + mt * 2048 + cA);
                ldsm4(am[mt], aM + mt * 2048 + cA);
                ldsm4(al[mt], aL + mt * 2048 + cA);
            }
            uint32_t bh[2][4], bm[2][4], bl[2][4], bhp[2][4], bmp[2][4];
#pragma unroll
            for (int np = 0; np < 2; np++) {
                ldsm4(bh[np], bH + np * 2048 + cB);
                ldsm4(bm[np], bM + np * 2048 + cB);
                ldsm4(bl[np], bL + np * 2048 + cB);
#pragma unroll
                for (int r = 0; r < 4; r++) {
                    bhp[np][r] = derive_c8(bh[np][r]);
                    bmp[np][r] = derive_c8(bm[np][r]);
                }
            }

            // re chains (shared acc[0]): hh, hm, mh, hl, lh, mm
#pragma unroll
            for (int mt = 0; mt < 4; mt++)
#pragma unroll
                for (int np = 0; np < 2; np++)
#pragma unroll
                    for (int h = 0; h < 2; h++)
                        mma_fp8(acc[0][mt][np * 2 + h], ah[mt],
                                bh[np][h * 2], bh[np][h * 2 + 1]);
#pragma unroll
            for (int mt = 0; mt < 4; mt++)
#pragma unroll
                for (int np = 0; np < 2; np++)
#pragma unroll
                    for (int h = 0; h < 2; h++)
                        mma_fp8(acc[0][mt][np * 2 + h], ah[mt],
                                bm[np][h * 2], bm[np][h * 2 + 1]);
#pragma unroll
            for (int mt = 0; mt < 4; mt++)
#pragma unroll
                for (int np = 0; np < 2; np++)
#pragma unroll
                    for (int h = 0; h < 2; h++)
                        mma_fp8(acc[0][mt][np * 2 + h], am[mt],
                                bh[np][h * 2], bh[np][h * 2 + 1]);
#pragma unroll
            for (int mt = 0; mt < 4; mt++)
#pragma unroll
                for (int np = 0; np < 2; np++)
#pragma unroll
                    for (int h = 0; h < 2; h++)
                        mma_fp8(acc[0][mt][np * 2 + h], ah[mt],
                                bl[np][h * 2], bl[np][h * 2 + 1]);
#pragma unroll
            for (int mt = 0; mt < 4; mt++)
#pragma unroll
                for (int np = 0; np < 2; np++)
#pragma unroll
                    for (int h = 0; h < 2; h++)
                        mma_fp8(acc[0][mt][np * 2 + h], al[mt],
                                bh[np][h * 2], bh[np][h * 2 + 1]);
#pragma unroll
            for (int mt = 0; mt < 4; mt++)
#pragma unroll
                for (int np = 0; np < 2; np++)
#pragma unroll
                    for (int h = 0; h < 2; h++)
                        mma_fp8(acc[0][mt][np * 2 + h], am[mt],
                                bm[np][h * 2], bm[np][h * 2 + 1]);
            // im chains (shared acc[1]): hh', hm', mh'
#pragma unroll
            for (int mt = 0; mt < 4; mt++)
#pragma unroll
                for (int np = 0; np < 2; np++)
#pragma unroll
                    for (int h = 0; h < 2; h++)
                        mma_fp8(acc[1][mt][np * 2 + h], ah[mt],
                                bhp[np][h * 2], bhp[np][h * 2 + 1]);
#pragma unroll
            for (int mt = 0; mt < 4; mt++)
#pragma unroll
                for (int np = 0; np < 2; np++)
#pragma unroll
                    for (int h = 0; h < 2; h++)
                        mma_fp8(acc[1][mt][np * 2 + h], ah[mt],
                                bmp[np][h * 2], bmp[np][h * 2 + 1]);
#pragma unroll
            for (int mt = 0; mt < 4; mt++)
#pragma unroll
                for (int np = 0; np < 2; np++)
#pragma unroll
                    for (int h = 0; h < 2; h++)
                        mma_fp8(acc[1][mt][np * 2 + h], am[mt],
                                bhp[np][h * 2], bhp[np][h * 2 + 1]);
        }

        __syncthreads();

        int nk = kt + NSTAGE;
        if (nk < NKT) {
#pragma unroll
            for (int tt = 0; tt < 6; tt++) {
#pragma unroll
                for (int u = 0; u < 4; u++) {
                    int p = u * 256 + tid;
                    int rr = p >> 3, cc = p & 7;
                    uint32_t dst = sb + tt * TILE_B + (uint32_t)rr * 128 +
                                   (((uint32_t)cc * 16) ^ (((uint32_t)rr & 7) << 4));
                    cp_async16(dst, gsrc[tt] + (size_t)rr * KROWB + nk * 128 + cc * 16);
                }
            }
        }
        CP_COMMIT();
    }

    // ---------------- epilogue: K = (re/256)^2 + (im/256)^2 -------------
    CP_WAIT0();
    __syncthreads();                      // smem tiles dead; reuse for transpose

    const float s = 1.0f / 256.0f;
    float* T = (float*)smem;              // [128 cols][132 pitch] local transpose
    const int r0 = bi * 128 + wm * 64 + (lane >> 2);
    const int c0 = bj * 128 + wn * 32 + (lane & 3) * 2;
    const int rl0 = wm * 64 + (lane >> 2);
    const int cl0 = wn * 32 + (lane & 3) * 2;
#pragma unroll
    for (int mt = 0; mt < 4; mt++) {
#pragma unroll
        for (int nt = 0; nt < 4; nt++) {
            int row = r0 + mt * 16;
            int col = c0 + nt * 8;
            float re0 = acc[0][mt][nt][0] * s, im0 = acc[1][mt][nt][0] * s;
            float re1 = acc[0][mt][nt][1] * s, im1 = acc[1][mt][nt][1] * s;
            float re2 = acc[0][mt][nt][2] * s, im2 = acc[1][mt][nt][2] * s;
            float re3 = acc[0][mt][nt][3] * s, im3 = acc[1][mt][nt][3] * s;
            float v00 = re0 * re0 + im0 * im0;
            float v01 = re1 * re1 + im1 * im1;
            float v10 = re2 * re2 + im2 * im2;
            float v11 = re3 * re3 + im3 * im3;
            *(float2*)(K + (size_t)row * BSZ + col)       = make_float2(v00, v01);
            *(float2*)(K + (size_t)(row + 8) * BSZ + col) = make_float2(v10, v11);
            if (bi != bj) {
                int rr = rl0 + mt * 16, cc = cl0 + nt * 8;
                T[cc * 132 + rr]           = v00;
                T[(cc + 1) * 132 + rr]     = v01;
                T[cc * 132 + rr + 8]       = v10;
                T[(cc + 1) * 132 + rr + 8] = v11;
            }
        }
    }
    __syncthreads();
    if (bi != bj) {
        int c = tid >> 1, half = tid & 1;
        float4* dst = (float4*)(K + (size_t)(bj * 128 + c) * BSZ + bi * 128 + half * 64);
        const float* src = T + c * 132 + half * 64;
#pragma unroll
        for (int i = 0; i < 16; i++)
            dst[i] = make_float4(src[4 * i], src[4 * i + 1],
                                 src[4 * i + 2], src[4 * i + 3]);
    }
}

// -------------------------------------------------------------------------
extern "C" void kernel_launch(void* const* d_in, const int* in_sizes, int n_in,
                              void* d_out, int out_size) {
    const float* X      = (const float*)d_in[0];   // (4096, 12)
    const float* params = (const float*)d_in[1];   // (5, 12, 3)
    float* K = (float*)d_out;                      // (4096, 4096)

    cudaFuncSetAttribute(k_gram_mma, cudaFuncAttributeMaxDynamicSharedMemorySize,
                         GRAM_SMEM);

    k_psi0    <<<1,    1024>>>(params);
    k_states  <<<BSZ,  256>>>(X, params);
    k_gram_mma<<<NBLK, GRAM_THREADS, GRAM_SMEM>>>(K);
}

// round 7
// speedup vs baseline: 3.7334x; 3.7334x over previous
#include <cuda_runtime.h>
#include <cuda_bf16.h>
#include <math.h>
#include <cstdint>

#define NQ       12
#define NLAYERS  5
#define DIM      4096
#define BSZ      4096

// ---------------- device scratch (no allocations allowed) ----------------
__device__ float2 g_psi0[DIM];
// bf16 split operands, K interleaved (re,im) per complex element:
//   A = [re, im],  hi + lo split. Imag-operand C = [-im, re] derived in-reg.
__device__ __align__(128) __nv_bfloat162 g_Ah[(size_t)BSZ * DIM];
__device__ __align__(128) __nv_bfloat162 g_Al[(size_t)BSZ * DIM];

__device__ __forceinline__ float2 cmul(float2 a, float2 b) {
    return make_float2(a.x * b.x - a.y * b.y, a.x * b.y + a.y * b.x);
}
__device__ __forceinline__ float2 cadd(float2 a, float2 b) {
    return make_float2(a.x + b.x, a.y + b.y);
}

// Reference einsum 'st,blsr->bltr' applies U^T. T = U^T.
__device__ __forceinline__ void make_UT(float ph, float th, float lm,
                                        float2& T00, float2& T01,
                                        float2& T10, float2& T11) {
    float ct = cosf(0.5f * th), st = sinf(0.5f * th);
    float ap = 0.5f * (lm + ph), am = 0.5f * (lm - ph);
    float cap = cosf(ap), sap = sinf(ap);
    float cam = cosf(am), sam = sinf(am);
    float2 U00 = make_float2( ct * cap, -ct * sap);
    float2 U01 = make_float2(-st * cam,  st * sam);
    float2 U10 = make_float2( st * cam,  st * sam);
    float2 U11 = make_float2( ct * cap,  ct * sap);
    T00 = U00; T01 = U10; T10 = U01; T11 = U11;
}

// ---------------- Kernel A: data-independent prefix (layers 0..3) --------
__global__ void k_psi0(const float* __restrict__ params) {
    __shared__ float2 st[DIM];
    __shared__ float2 gates[48][4];      // precomputed T matrices
    int tid = threadIdx.x, nt = blockDim.x;  // nt = 1024

    if (tid < 48) {
        const float* p = params + tid * 3;   // (l*12+q)*3, l<4
        float2 T00, T01, T10, T11;
        make_UT(p[0], p[1], p[2], T00, T01, T10, T11);
        gates[tid][0] = T00; gates[tid][1] = T01;
        gates[tid][2] = T10; gates[tid][3] = T11;
    }
    for (int i = tid; i < DIM; i += nt)
        st[i] = make_float2(i == 0 ? 1.0f : 0.0f, 0.0f);
    __syncthreads();

    for (int l = 0; l < NLAYERS - 1; l++) {
        for (int q = 0; q < NQ; q++) {
            float2 T00 = gates[l * NQ + q][0], T01 = gates[l * NQ + q][1];
            float2 T10 = gates[l * NQ + q][2], T11 = gates[l * NQ + q][3];
            int mask = 1 << (NQ - 1 - q);
            for (int pi = tid; pi < DIM / 2; pi += nt) {
                int low = pi & (mask - 1);
                int hi  = (pi & ~(mask - 1)) << 1;
                int i0 = hi | low, i1 = i0 | mask;
                float2 s0 = st[i0], s1 = st[i1];
                st[i0] = cadd(cmul(T00, s0), cmul(T01, s1));
                st[i1] = cadd(cmul(T10, s0), cmul(T11, s1));
            }
            __syncthreads();
        }
        // composed CNOT permutation, single sweep
        {
            float2 tmp[4];
#pragma unroll
            for (int u = 0; u < 4; u++) {
                int idx = u * 1024 + tid;
                int j = idx;
#pragma unroll
                for (int q = NQ - 2; q >= 0; q--) {
                    int cb = 1 << (NQ - 1 - q);
                    int tb = 1 << (NQ - 2 - q);
                    if (j & cb) j ^= tb;
                }
                tmp[u] = st[j];
            }
            __syncthreads();
#pragma unroll
            for (int u = 0; u < 4; u++)
                st[u * 1024 + tid] = tmp[u];
            __syncthreads();
        }
    }
    for (int i = tid; i < DIM; i += nt) g_psi0[i] = st[i];
}

// ---------------- Kernel B: per-sample layer-4 gates + bf16 split --------
__global__ void k_states(const float* __restrict__ X,
                         const float* __restrict__ params) {
    __shared__ float2 st[DIM];
    int i = blockIdx.x, tid = threadIdx.x, nt = blockDim.x;
    for (int k = tid; k < DIM; k += nt) st[k] = g_psi0[k];
    __syncthreads();

    for (int q = 0; q < NQ; q++) {
        const float* p = params + ((NLAYERS - 1) * NQ + q) * 3;
        float2 T00, T01, T10, T11;
        make_UT(p[0], p[1], p[2], T00, T01, T10, T11);
        float x = X[i * NQ + q];
        float gc = cosf(0.5f * x), gs = sinf(0.5f * x);
        // V = G^T * T
        float2 V00 = make_float2(gc * T00.x + gs * T10.x, gc * T00.y + gs * T10.y);
        float2 V01 = make_float2(gc * T01.x + gs * T11.x, gc * T01.y + gs * T11.y);
        float2 V10 = make_float2(-gs * T00.x + gc * T10.x, -gs * T00.y + gc * T10.y);
        float2 V11 = make_float2(-gs * T01.x + gc * T11.x, -gs * T01.y + gc * T11.y);

        int mask = 1 << (NQ - 1 - q);
        for (int pi = tid; pi < DIM / 2; pi += nt) {
            int low = pi & (mask - 1);
            int hi  = (pi & ~(mask - 1)) << 1;
            int i0 = hi | low, i1 = i0 | mask;
            float2 s0 = st[i0], s1 = st[i1];
            st[i0] = cadd(cmul(V00, s0), cmul(V01, s1));
            st[i1] = cadd(cmul(V10, s0), cmul(V11, s1));
        }
        __syncthreads();
    }

    size_t rowoff = (size_t)i * DIM;
    for (int k = tid; k < DIM; k += nt) {
        float re = st[k].x, im = st[k].y;
        __nv_bfloat16 hr = __float2bfloat16_rn(re);
        __nv_bfloat16 hi = __float2bfloat16_rn(im);
        __nv_bfloat16 lr = __float2bfloat16_rn(re - __bfloat162float(hr));
        __nv_bfloat16 li = __float2bfloat16_rn(im - __bfloat162float(hi));
        __nv_bfloat162 ah; ah.x = hr; ah.y = hi;
        __nv_bfloat162 al; al.x = lr; al.y = li;
        g_Ah[rowoff + k] = ah;
        g_Al[rowoff + k] = al;
    }
}

// =============  Kernel C: HMMA (mma.sync bf16) split Gram  ================
// re: Ah.Ah + Ah.Al   (2 chains; one-sided lo term suffices)
// im: Ah.Ch           (1 chain; Ch = (-im,re) derived in-register)
// A-side lo never used -> 3 SMEM tiles/stage: {Ah_i, Ah_j, Al_j}.
// K_out = re^2 + im^2.  Triangular 128x128 tiles.
#define KELEMS    8192
#define NKT       128                   // 8192 / 64 bf16 per chunk
#define TILE_B    16384                 // 128 rows x 128 bytes
#define STAGE_B   (3 * TILE_B)          // 48KB
#define NSTAGE    4
#define GRAM_SMEM (NSTAGE * STAGE_B)    // 192KB
#define GRAM_THREADS 256
#define NTILE (DIM / 128)               // 32
#define NBLK  (NTILE * (NTILE + 1) / 2) // 528

__device__ __forceinline__ uint32_t smem_u32(const void* p) {
    return (uint32_t)__cvta_generic_to_shared(p);
}
__device__ __forceinline__ void cp_async16(uint32_t dst, const void* src) {
    asm volatile("cp.async.cg.shared.global [%0], [%1], 16;" :: "r"(dst), "l"(src));
}
#define CP_COMMIT()  asm volatile("cp.async.commit_group;" ::: "memory")
#define CP_WAIT3()   asm volatile("cp.async.wait_group 3;" ::: "memory")
#define CP_WAIT0()   asm volatile("cp.async.wait_group 0;" ::: "memory")

__device__ __forceinline__ void ldsm4(uint32_t* r, uint32_t addr) {
    asm volatile("ldmatrix.sync.aligned.m8n8.x4.shared.b16 {%0,%1,%2,%3}, [%4];"
        : "=r"(r[0]), "=r"(r[1]), "=r"(r[2]), "=r"(r[3]) : "r"(addr));
}
__device__ __forceinline__ void mma_bf16(float* c, const uint32_t* a,
                                         uint32_t b0, uint32_t b1) {
    asm volatile(
        "mma.sync.aligned.m16n8k16.row.col.f32.bf16.bf16.f32 "
        "{%0,%1,%2,%3}, {%4,%5,%6,%7}, {%8,%9}, {%0,%1,%2,%3};"
        : "+f"(c[0]), "+f"(c[1]), "+f"(c[2]), "+f"(c[3])
        : "r"(a[0]), "r"(a[1]), "r"(a[2]), "r"(a[3]), "r"(b0), "r"(b1));
}
// (re,im) packed pair -> (-im, re)
__device__ __forceinline__ uint32_t derive_c(uint32_t b) {
    return __byte_perm(b, b, 0x1032) ^ 0x00008000u;
}

__global__ void __launch_bounds__(GRAM_THREADS, 1)
k_gram_mma(float* __restrict__ K) {
    extern __shared__ __align__(1024) char smem[];
    const uint32_t smem_base = smem_u32(smem);
    const int tid  = threadIdx.x;
    const int wid  = tid >> 5;
    const int lane = tid & 31;
    const int wm = wid >> 2;            // 0..1  (64-row slab)
    const int wn = wid & 3;             // 0..3  (32-col slab)

    // triangular tile mapping (bi <= bj)
    int t = blockIdx.x;
    int bj = (int)((sqrtf(8.0f * (float)t + 1.0f) - 1.0f) * 0.5f);
    while ((bj + 1) * (bj + 2) / 2 <= t) bj++;
    while (bj * (bj + 1) / 2 > t) bj--;
    int bi = t - bj * (bj + 1) / 2;

    const char* gsrc[3];
    gsrc[0] = (const char*)g_Ah + (size_t)bi * 128 * 16384;  // Ah_i
    gsrc[1] = (const char*)g_Ah + (size_t)bj * 128 * 16384;  // Ah_j
    gsrc[2] = (const char*)g_Al + (size_t)bj * 128 * 16384;  // Al_j

    // ldmatrix per-thread geometry
    const int mat = lane >> 3, rl = lane & 7;
    const int rowA_base = wm * 64 + (mat & 1) * 8 + rl;   // + mt*16
    const uint32_t kselA = (uint32_t)((mat >> 1) * 16);
    const uint32_t xA = (uint32_t)(rowA_base & 7) << 4;
    const int rowB_base = wn * 32 + (mat >> 1) * 8 + rl;  // + np*16
    const uint32_t kselB = (uint32_t)((mat & 1) * 16);
    const uint32_t xB = (uint32_t)(rowB_base & 7) << 4;

    float acc[2][4][4][4];
#pragma unroll
    for (int e = 0; e < 2; e++)
#pragma unroll
        for (int mt = 0; mt < 4; mt++)
#pragma unroll
            for (int nt = 0; nt < 4; nt++)
#pragma unroll
                for (int r = 0; r < 4; r++) acc[e][mt][nt][r] = 0.f;

    // ---------------- prologue: fill 4 stages --------------------------
#pragma unroll 1
    for (int pk = 0; pk < NSTAGE; pk++) {
        uint32_t sb = smem_base + pk * STAGE_B;
#pragma unroll
        for (int tt = 0; tt < 3; tt++) {
#pragma unroll
            for (int u = 0; u < 4; u++) {
                int p = u * 256 + tid;
                int rr = p >> 3, cc = p & 7;
                uint32_t dst = sb + tt * TILE_B + (uint32_t)rr * 128 +
                               (((uint32_t)cc * 16) ^ (((uint32_t)rr & 7) << 4));
                cp_async16(dst, gsrc[tt] + (size_t)rr * 16384 + pk * 128 + cc * 16);
            }
        }
        CP_COMMIT();
    }

    // ---------------- main loop ----------------------------------------
#pragma unroll 1
    for (int kt = 0; kt < NKT; kt++) {
        CP_WAIT3();
        __syncthreads();

        uint32_t sb = smem_base + (kt & 3) * STAGE_B;
        uint32_t aH = sb + (uint32_t)rowA_base * 128;
        uint32_t bH = sb + TILE_B + (uint32_t)rowB_base * 128;
        uint32_t bL = sb + 2 * TILE_B + (uint32_t)rowB_base * 128;

#pragma unroll
        for (int ks = 0; ks < 4; ks++) {
            uint32_t cA = ((uint32_t)(ks * 32) + kselA) ^ xA;
            uint32_t cB = ((uint32_t)(ks * 32) + kselB) ^ xB;

            uint32_t ah[4][4];
#pragma unroll
            for (int mt = 0; mt < 4; mt++)
                ldsm4(ah[mt], aH + mt * 2048 + cA);
            uint32_t bh[2][4], bl[2][4], bhp[2][4];
#pragma unroll
            for (int np = 0; np < 2; np++) {
                ldsm4(bh[np], bH + np * 2048 + cB);
                ldsm4(bl[np], bL + np * 2048 + cB);
#pragma unroll
                for (int r = 0; r < 4; r++)
                    bhp[np][r] = derive_c(bh[np][r]);
            }

            // chain-ordered: consecutive MMAs always hit distinct accs
#pragma unroll
            for (int mt = 0; mt < 4; mt++)          // re: Ah.Ah
#pragma unroll
                for (int np = 0; np < 2; np++)
#pragma unroll
                    for (int h = 0; h < 2; h++)
                        mma_bf16(acc[0][mt][np * 2 + h], ah[mt],
                                 bh[np][h * 2], bh[np][h * 2 + 1]);
#pragma unroll
            for (int mt = 0; mt < 4; mt++)          // re: Ah.Al
#pragma unroll
                for (int np = 0; np < 2; np++)
#pragma unroll
                    for (int h = 0; h < 2; h++)
                        mma_bf16(acc[0][mt][np * 2 + h], ah[mt],
                                 bl[np][h * 2], bl[np][h * 2 + 1]);
#pragma unroll
            for (int mt = 0; mt < 4; mt++)          // im: Ah.Ch
#pragma unroll
                for (int np = 0; np < 2; np++)
#pragma unroll
                    for (int h = 0; h < 2; h++)
                        mma_bf16(acc[1][mt][np * 2 + h], ah[mt],
                                 bhp[np][h * 2], bhp[np][h * 2 + 1]);
        }

        __syncthreads();

        int nk = kt + NSTAGE;
        if (nk < NKT) {
#pragma unroll
            for (int tt = 0; tt < 3; tt++) {
#pragma unroll
                for (int u = 0; u < 4; u++) {
                    int p = u * 256 + tid;
                    int rr = p >> 3, cc = p & 7;
                    uint32_t dst = sb + tt * TILE_B + (uint32_t)rr * 128 +
                                   (((uint32_t)cc * 16) ^ (((uint32_t)rr & 7) << 4));
                    cp_async16(dst, gsrc[tt] + (size_t)rr * 16384 + nk * 128 + cc * 16);
                }
            }
        }
        CP_COMMIT();
    }

    // ---------------- epilogue: K = re^2 + im^2 ------------------------
    CP_WAIT0();
    __syncthreads();                      // smem tiles dead; reuse for transpose

    float* T = (float*)smem;              // [128 cols][132 pitch] local transpose
    const int r0 = bi * 128 + wm * 64 + (lane >> 2);
    const int c0 = bj * 128 + wn * 32 + (lane & 3) * 2;
    const int rl0 = wm * 64 + (lane >> 2);
    const int cl0 = wn * 32 + (lane & 3) * 2;
#pragma unroll
    for (int mt = 0; mt < 4; mt++) {
#pragma unroll
        for (int nt = 0; nt < 4; nt++) {
            int row = r0 + mt * 16;
            int col = c0 + nt * 8;
            float* re = acc[0][mt][nt];
            float* im = acc[1][mt][nt];
            float v00 = re[0] * re[0] + im[0] * im[0];
            float v01 = re[1] * re[1] + im[1] * im[1];
            float v10 = re[2] * re[2] + im[2] * im[2];
            float v11 = re[3] * re[3] + im[3] * im[3];
            *(float2*)(K + (size_t)row * BSZ + col)       = make_float2(v00, v01);
            *(float2*)(K + (size_t)(row + 8) * BSZ + col) = make_float2(v10, v11);
            if (bi != bj) {
                int rr = rl0 + mt * 16, cc = cl0 + nt * 8;
                T[cc * 132 + rr]           = v00;
                T[(cc + 1) * 132 + rr]     = v01;
                T[cc * 132 + rr + 8]       = v10;
                T[(cc + 1) * 132 + rr + 8] = v11;
            }
        }
    }
    __syncthreads();
    if (bi != bj) {
        // coalesced mirror: row c of T -> K[(bj*128+c)][bi*128 ..]
        int c = tid >> 1, half = tid & 1;
        float4* dst = (float4*)(K + (size_t)(bj * 128 + c) * BSZ + bi * 128 + half * 64);
        const float* src = T + c * 132 + half * 64;
#pragma unroll
        for (int i = 0; i < 16; i++)
            dst[i] = make_float4(src[4 * i], src[4 * i + 1],
                                 src[4 * i + 2], src[4 * i + 3]);
    }
}

// -------------------------------------------------------------------------
extern "C" void kernel_launch(void* const* d_in, const int* in_sizes, int n_in,
                              void* d_out, int out_size) {
    const float* X      = (const float*)d_in[0];   // (4096, 12)
    const float* params = (const float*)d_in[1];   // (5, 12, 3)
    float* K = (float*)d_out;                      // (4096, 4096)

    cudaFuncSetAttribute(k_gram_mma, cudaFuncAttributeMaxDynamicSharedMemorySize,
                         GRAM_SMEM);

    k_psi0    <<<1,    1024>>>(params);
    k_states  <<<BSZ,  256>>>(X, params);
    k_gram_mma<<<NBLK, GRAM_THREADS, GRAM_SMEM>>>(K);
}

// round 8
// speedup vs baseline: 4.9024x; 1.3131x over previous
#include <cuda_runtime.h>
#include <cuda_fp16.h>
#include <math.h>
#include <cstdint>

#define NQ       12
#define NLAYERS  5
#define DIM      4096
#define BSZ      4096

// ---------------- device scratch (no allocations allowed) ----------------
__device__ float2 g_psi0[DIM];
// f16 states, K interleaved (re,im) per complex element. Imag-operand
// C = [-im, re] is derived in-register inside the GEMM (no lo arrays:
// f16's 11-bit mantissa makes the correction chains unnecessary).
__device__ __align__(128) __half2 g_Fh[(size_t)BSZ * DIM];

__device__ __forceinline__ float2 cmul(float2 a, float2 b) {
    return make_float2(a.x * b.x - a.y * b.y, a.x * b.y + a.y * b.x);
}
__device__ __forceinline__ float2 cadd(float2 a, float2 b) {
    return make_float2(a.x + b.x, a.y + b.y);
}

// Reference einsum 'st,blsr->bltr' applies U^T. T = U^T.
__device__ __forceinline__ void make_UT(float ph, float th, float lm,
                                        float2& T00, float2& T01,
                                        float2& T10, float2& T11) {
    float ct = cosf(0.5f * th), st = sinf(0.5f * th);
    float ap = 0.5f * (lm + ph), am = 0.5f * (lm - ph);
    float cap = cosf(ap), sap = sinf(ap);
    float cam = cosf(am), sam = sinf(am);
    float2 U00 = make_float2( ct * cap, -ct * sap);
    float2 U01 = make_float2(-st * cam,  st * sam);
    float2 U10 = make_float2( st * cam,  st * sam);
    float2 U11 = make_float2( ct * cap,  ct * sap);
    T00 = U00; T01 = U10; T10 = U01; T11 = U11;
}

// ---------------- Kernel A: data-independent prefix (layers 0..3) --------
__global__ void k_psi0(const float* __restrict__ params) {
    __shared__ float2 st[DIM];
    __shared__ float2 gates[48][4];      // precomputed T matrices
    int tid = threadIdx.x, nt = blockDim.x;  // nt = 1024

    if (tid < 48) {
        const float* p = params + tid * 3;   // (l*12+q)*3, l<4
        float2 T00, T01, T10, T11;
        make_UT(p[0], p[1], p[2], T00, T01, T10, T11);
        gates[tid][0] = T00; gates[tid][1] = T01;
        gates[tid][2] = T10; gates[tid][3] = T11;
    }
    for (int i = tid; i < DIM; i += nt)
        st[i] = make_float2(i == 0 ? 1.0f : 0.0f, 0.0f);
    __syncthreads();

    for (int l = 0; l < NLAYERS - 1; l++) {
        for (int q = 0; q < NQ; q++) {
            float2 T00 = gates[l * NQ + q][0], T01 = gates[l * NQ + q][1];
            float2 T10 = gates[l * NQ + q][2], T11 = gates[l * NQ + q][3];
            int mask = 1 << (NQ - 1 - q);
            for (int pi = tid; pi < DIM / 2; pi += nt) {
                int low = pi & (mask - 1);
                int hi  = (pi & ~(mask - 1)) << 1;
                int i0 = hi | low, i1 = i0 | mask;
                float2 s0 = st[i0], s1 = st[i1];
                st[i0] = cadd(cmul(T00, s0), cmul(T01, s1));
                st[i1] = cadd(cmul(T10, s0), cmul(T11, s1));
            }
            __syncthreads();
        }
        // composed CNOT permutation, single sweep
        {
            float2 tmp[4];
#pragma unroll
            for (int u = 0; u < 4; u++) {
                int idx = u * 1024 + tid;
                int j = idx;
#pragma unroll
                for (int q = NQ - 2; q >= 0; q--) {
                    int cb = 1 << (NQ - 1 - q);
                    int tb = 1 << (NQ - 2 - q);
                    if (j & cb) j ^= tb;
                }
                tmp[u] = st[j];
            }
            __syncthreads();
#pragma unroll
            for (int u = 0; u < 4; u++)
                st[u * 1024 + tid] = tmp[u];
            __syncthreads();
        }
    }
    for (int i = tid; i < DIM; i += nt) g_psi0[i] = st[i];
}

// ---------------- Kernel B: per-sample layer-4 gates + f16 pack ----------
__global__ void k_states(const float* __restrict__ X,
                         const float* __restrict__ params) {
    __shared__ float2 st[DIM];
    int i = blockIdx.x, tid = threadIdx.x, nt = blockDim.x;
    for (int k = tid; k < DIM; k += nt) st[k] = g_psi0[k];
    __syncthreads();

    for (int q = 0; q < NQ; q++) {
        const float* p = params + ((NLAYERS - 1) * NQ + q) * 3;
        float2 T00, T01, T10, T11;
        make_UT(p[0], p[1], p[2], T00, T01, T10, T11);
        float x = X[i * NQ + q];
        float gc = cosf(0.5f * x), gs = sinf(0.5f * x);
        // V = G^T * T
        float2 V00 = make_float2(gc * T00.x + gs * T10.x, gc * T00.y + gs * T10.y);
        float2 V01 = make_float2(gc * T01.x + gs * T11.x, gc * T01.y + gs * T11.y);
        float2 V10 = make_float2(-gs * T00.x + gc * T10.x, -gs * T00.y + gc * T10.y);
        float2 V11 = make_float2(-gs * T01.x + gc * T11.x, -gs * T01.y + gc * T11.y);

        int mask = 1 << (NQ - 1 - q);
        for (int pi = tid; pi < DIM / 2; pi += nt) {
            int low = pi & (mask - 1);
            int hi  = (pi & ~(mask - 1)) << 1;
            int i0 = hi | low, i1 = i0 | mask;
            float2 s0 = st[i0], s1 = st[i1];
            st[i0] = cadd(cmul(V00, s0), cmul(V01, s1));
            st[i1] = cadd(cmul(V10, s0), cmul(V11, s1));
        }
        __syncthreads();
    }

    size_t rowoff = (size_t)i * DIM;
    for (int k = tid; k < DIM; k += nt)
        g_Fh[rowoff + k] = __floats2half2_rn(st[k].x, st[k].y);
}

// =============  Kernel C: HMMA (mma.sync f16) Gram  =======================
// re: F.F^T ; im: F.C^T  (C = (-im,re) derived in-register)
// K_out = re^2 + im^2.  Triangular 128x128 tiles. f16's 11-bit mantissa
// keeps the quadrature error ~3e-4 without split-correction chains.
#define KELEMS    8192
#define NKT       128                   // 8192 / 64 f16 per chunk
#define TILE_B    16384                 // 128 rows x 128 bytes
#define STAGE_B   (2 * TILE_B)          // {F_i, F_j} = 32KB
#define NSTAGE    4
#define GRAM_SMEM (NSTAGE * STAGE_B)    // 128KB
#define GRAM_THREADS 256
#define NTILE (DIM / 128)               // 32
#define NBLK  (NTILE * (NTILE + 1) / 2) // 528

__device__ __forceinline__ uint32_t smem_u32(const void* p) {
    return (uint32_t)__cvta_generic_to_shared(p);
}
__device__ __forceinline__ void cp_async16(uint32_t dst, const void* src) {
    asm volatile("cp.async.cg.shared.global [%0], [%1], 16;" :: "r"(dst), "l"(src));
}
#define CP_COMMIT()  asm volatile("cp.async.commit_group;" ::: "memory")
#define CP_WAIT3()   asm volatile("cp.async.wait_group 3;" ::: "memory")
#define CP_WAIT0()   asm volatile("cp.async.wait_group 0;" ::: "memory")

__device__ __forceinline__ void ldsm4(uint32_t* r, uint32_t addr) {
    asm volatile("ldmatrix.sync.aligned.m8n8.x4.shared.b16 {%0,%1,%2,%3}, [%4];"
        : "=r"(r[0]), "=r"(r[1]), "=r"(r[2]), "=r"(r[3]) : "r"(addr));
}
__device__ __forceinline__ void mma_f16(float* c, const uint32_t* a,
                                        uint32_t b0, uint32_t b1) {
    asm volatile(
        "mma.sync.aligned.m16n8k16.row.col.f32.f16.f16.f32 "
        "{%0,%1,%2,%3}, {%4,%5,%6,%7}, {%8,%9}, {%0,%1,%2,%3};"
        : "+f"(c[0]), "+f"(c[1]), "+f"(c[2]), "+f"(c[3])
        : "r"(a[0]), "r"(a[1]), "r"(a[2]), "r"(a[3]), "r"(b0), "r"(b1));
}
// (re,im) packed f16 pair -> (-im, re)
__device__ __forceinline__ uint32_t derive_c(uint32_t b) {
    return __byte_perm(b, b, 0x1032) ^ 0x00008000u;
}

__global__ void __launch_bounds__(GRAM_THREADS, 1)
k_gram_mma(float* __restrict__ K) {
    extern __shared__ __align__(1024) char smem[];
    const uint32_t smem_base = smem_u32(smem);
    const int tid  = threadIdx.x;
    const int wid  = tid >> 5;
    const int lane = tid & 31;
    const int wm = wid >> 2;            // 0..1  (64-row slab)
    const int wn = wid & 3;             // 0..3  (32-col slab)

    // triangular tile mapping (bi <= bj)
    int t = blockIdx.x;
    int bj = (int)((sqrtf(8.0f * (float)t + 1.0f) - 1.0f) * 0.5f);
    while ((bj + 1) * (bj + 2) / 2 <= t) bj++;
    while (bj * (bj + 1) / 2 > t) bj--;
    int bi = t - bj * (bj + 1) / 2;

    const char* gsrc[2];
    gsrc[0] = (const char*)g_Fh + (size_t)bi * 128 * 16384;  // F_i
    gsrc[1] = (const char*)g_Fh + (size_t)bj * 128 * 16384;  // F_j

    // ldmatrix per-thread geometry
    const int mat = lane >> 3, rl = lane & 7;
    const int rowA_base = wm * 64 + (mat & 1) * 8 + rl;   // + mt*16
    const uint32_t kselA = (uint32_t)((mat >> 1) * 16);
    const uint32_t xA = (uint32_t)(rowA_base & 7) << 4;
    const int rowB_base = wn * 32 + (mat >> 1) * 8 + rl;  // + np*16
    const uint32_t kselB = (uint32_t)((mat & 1) * 16);
    const uint32_t xB = (uint32_t)(rowB_base & 7) << 4;

    float acc[2][4][4][4];
#pragma unroll
    for (int e = 0; e < 2; e++)
#pragma unroll
        for (int mt = 0; mt < 4; mt++)
#pragma unroll
            for (int nt = 0; nt < 4; nt++)
#pragma unroll
                for (int r = 0; r < 4; r++) acc[e][mt][nt][r] = 0.f;

    // ---------------- prologue: fill 4 stages --------------------------
#pragma unroll 1
    for (int pk = 0; pk < NSTAGE; pk++) {
        uint32_t sb = smem_base + pk * STAGE_B;
#pragma unroll
        for (int tt = 0; tt < 2; tt++) {
#pragma unroll
            for (int u = 0; u < 4; u++) {
                int p = u * 256 + tid;
                int rr = p >> 3, cc = p & 7;
                uint32_t dst = sb + tt * TILE_B + (uint32_t)rr * 128 +
                               (((uint32_t)cc * 16) ^ (((uint32_t)rr & 7) << 4));
                cp_async16(dst, gsrc[tt] + (size_t)rr * 16384 + pk * 128 + cc * 16);
            }
        }
        CP_COMMIT();
    }

    // ---------------- main loop ----------------------------------------
#pragma unroll 1
    for (int kt = 0; kt < NKT; kt++) {
        CP_WAIT3();
        __syncthreads();

        uint32_t sb = smem_base + (kt & 3) * STAGE_B;
        uint32_t aH = sb + (uint32_t)rowA_base * 128;
        uint32_t bH = sb + TILE_B + (uint32_t)rowB_base * 128;

#pragma unroll
        for (int ks = 0; ks < 4; ks++) {
            uint32_t cA = ((uint32_t)(ks * 32) + kselA) ^ xA;
            uint32_t cB = ((uint32_t)(ks * 32) + kselB) ^ xB;

            uint32_t ah[4][4];
#pragma unroll
            for (int mt = 0; mt < 4; mt++)
                ldsm4(ah[mt], aH + mt * 2048 + cA);
            uint32_t bh[2][4], bhp[2][4];
#pragma unroll
            for (int np = 0; np < 2; np++) {
                ldsm4(bh[np], bH + np * 2048 + cB);
#pragma unroll
                for (int r = 0; r < 4; r++)
                    bhp[np][r] = derive_c(bh[np][r]);
            }

            // chain-ordered: consecutive MMAs always hit distinct accs
#pragma unroll
            for (int mt = 0; mt < 4; mt++)          // re: F.F
#pragma unroll
                for (int np = 0; np < 2; np++)
#pragma unroll
                    for (int h = 0; h < 2; h++)
                        mma_f16(acc[0][mt][np * 2 + h], ah[mt],
                                bh[np][h * 2], bh[np][h * 2 + 1]);
#pragma unroll
            for (int mt = 0; mt < 4; mt++)          // im: F.C
#pragma unroll
                for (int np = 0; np < 2; np++)
#pragma unroll
                    for (int h = 0; h < 2; h++)
                        mma_f16(acc[1][mt][np * 2 + h], ah[mt],
                                bhp[np][h * 2], bhp[np][h * 2 + 1]);
        }

        __syncthreads();

        int nk = kt + NSTAGE;
        if (nk < NKT) {
#pragma unroll
            for (int tt = 0; tt < 2; tt++) {
#pragma unroll
                for (int u = 0; u < 4; u++) {
                    int p = u * 256 + tid;
                    int rr = p >> 3, cc = p & 7;
                    uint32_t dst = sb + tt * TILE_B + (uint32_t)rr * 128 +
                                   (((uint32_t)cc * 16) ^ (((uint32_t)rr & 7) << 4));
                    cp_async16(dst, gsrc[tt] + (size_t)rr * 16384 + nk * 128 + cc * 16);
                }
            }
        }
        CP_COMMIT();
    }

    // ---------------- epilogue: K = re^2 + im^2 ------------------------
    CP_WAIT0();
    __syncthreads();                      // smem tiles dead; reuse for transpose

    float* T = (float*)smem;              // [128 cols][132 pitch] local transpose
    const int r0 = bi * 128 + wm * 64 + (lane >> 2);
    const int c0 = bj * 128 + wn * 32 + (lane & 3) * 2;
    const int rl0 = wm * 64 + (lane >> 2);
    const int cl0 = wn * 32 + (lane & 3) * 2;
#pragma unroll
    for (int mt = 0; mt < 4; mt++) {
#pragma unroll
        for (int nt = 0; nt < 4; nt++) {
            int row = r0 + mt * 16;
            int col = c0 + nt * 8;
            float* re = acc[0][mt][nt];
            float* im = acc[1][mt][nt];
            float v00 = re[0] * re[0] + im[0] * im[0];
            float v01 = re[1] * re[1] + im[1] * im[1];
            float v10 = re[2] * re[2] + im[2] * im[2];
            float v11 = re[3] * re[3] + im[3] * im[3];
            *(float2*)(K + (size_t)row * BSZ + col)       = make_float2(v00, v01);
            *(float2*)(K + (size_t)(row + 8) * BSZ + col) = make_float2(v10, v11);
            if (bi != bj) {
                int rr = rl0 + mt * 16, cc = cl0 + nt * 8;
                T[cc * 132 + rr]           = v00;
                T[(cc + 1) * 132 + rr]     = v01;
                T[cc * 132 + rr + 8]       = v10;
                T[(cc + 1) * 132 + rr + 8] = v11;
            }
        }
    }
    __syncthreads();
    if (bi != bj) {
        // coalesced mirror: row c of T -> K[(bj*128+c)][bi*128 ..]
        int c = tid >> 1, half = tid & 1;
        float4* dst = (float4*)(K + (size_t)(bj * 128 + c) * BSZ + bi * 128 + half * 64);
        const float* src = T + c * 132 + half * 64;
#pragma unroll
        for (int i = 0; i < 16; i++)
            dst[i] = make_float4(src[4 * i], src[4 * i + 1],
                                 src[4 * i + 2], src[4 * i + 3]);
    }
}

// -------------------------------------------------------------------------
extern "C" void kernel_launch(void* const* d_in, const int* in_sizes, int n_in,
                              void* d_out, int out_size) {
    const float* X      = (const float*)d_in[0];   // (4096, 12)
    const float* params = (const float*)d_in[1];   // (5, 12, 3)
    float* K = (float*)d_out;                      // (4096, 4096)

    cudaFuncSetAttribute(k_gram_mma, cudaFuncAttributeMaxDynamicSharedMemorySize,
                         GRAM_SMEM);

    k_psi0    <<<1,    1024>>>(params);
    k_states  <<<BSZ,  256>>>(X, params);
    k_gram_mma<<<NBLK, GRAM_THREADS, GRAM_SMEM>>>(K);
}

// round 9
// speedup vs baseline: 5.8507x; 1.1934x over previous
#include <cuda_runtime.h>
#include <cuda_fp16.h>
#include <math.h>
#include <cstdint>

#define NQ       12
#define NLAYERS  5
#define DIM      4096
#define BSZ      4096

// ---------------- device scratch (no allocations allowed) ----------------
__device__ float2 g_psi0[DIM];
// Planar f16 feature arrays for the Gauss 3-mult complex Gram:
//   A0 = re, A1 = im, A2 = re+im, A4 = re-im.   K = 4096 reals per row.
__device__ __align__(128) __half g_A0[(size_t)BSZ * DIM];
__device__ __align__(128) __half g_A1[(size_t)BSZ * DIM];
__device__ __align__(128) __half g_A2[(size_t)BSZ * DIM];
__device__ __align__(128) __half g_A4[(size_t)BSZ * DIM];

__device__ __forceinline__ float2 cmul(float2 a, float2 b) {
    return make_float2(a.x * b.x - a.y * b.y, a.x * b.y + a.y * b.x);
}
__device__ __forceinline__ float2 cadd(float2 a, float2 b) {
    return make_float2(a.x + b.x, a.y + b.y);
}

// Reference einsum 'st,blsr->bltr' applies U^T. T = U^T.
__device__ __forceinline__ void make_UT(float ph, float th, float lm,
                                        float2& T00, float2& T01,
                                        float2& T10, float2& T11) {
    float ct = cosf(0.5f * th), st = sinf(0.5f * th);
    float ap = 0.5f * (lm + ph), am = 0.5f * (lm - ph);
    float cap = cosf(ap), sap = sinf(ap);
    float cam = cosf(am), sam = sinf(am);
    float2 U00 = make_float2( ct * cap, -ct * sap);
    float2 U01 = make_float2(-st * cam,  st * sam);
    float2 U10 = make_float2( st * cam,  st * sam);
    float2 U11 = make_float2( ct * cap,  ct * sap);
    T00 = U00; T01 = U10; T10 = U01; T11 = U11;
}

// ---------------- Kernel A: data-independent prefix (layers 0..3) --------
__global__ void k_psi0(const float* __restrict__ params) {
    __shared__ float2 st[DIM];
    __shared__ float2 gates[48][4];      // precomputed T matrices
    int tid = threadIdx.x, nt = blockDim.x;  // nt = 1024

    if (tid < 48) {
        const float* p = params + tid * 3;   // (l*12+q)*3, l<4
        float2 T00, T01, T10, T11;
        make_UT(p[0], p[1], p[2], T00, T01, T10, T11);
        gates[tid][0] = T00; gates[tid][1] = T01;
        gates[tid][2] = T10; gates[tid][3] = T11;
    }
    for (int i = tid; i < DIM; i += nt)
        st[i] = make_float2(i == 0 ? 1.0f : 0.0f, 0.0f);
    __syncthreads();

    for (int l = 0; l < NLAYERS - 1; l++) {
        for (int q = 0; q < NQ; q++) {
            float2 T00 = gates[l * NQ + q][0], T01 = gates[l * NQ + q][1];
            float2 T10 = gates[l * NQ + q][2], T11 = gates[l * NQ + q][3];
            int mask = 1 << (NQ - 1 - q);
            for (int pi = tid; pi < DIM / 2; pi += nt) {
                int low = pi & (mask - 1);
                int hi  = (pi & ~(mask - 1)) << 1;
                int i0 = hi | low, i1 = i0 | mask;
                float2 s0 = st[i0], s1 = st[i1];
                st[i0] = cadd(cmul(T00, s0), cmul(T01, s1));
                st[i1] = cadd(cmul(T10, s0), cmul(T11, s1));
            }
            __syncthreads();
        }
        // composed CNOT permutation, single sweep
        {
            float2 tmp[4];
#pragma unroll
            for (int u = 0; u < 4; u++) {
                int idx = u * 1024 + tid;
                int j = idx;
#pragma unroll
                for (int q = NQ - 2; q >= 0; q--) {
                    int cb = 1 << (NQ - 1 - q);
                    int tb = 1 << (NQ - 2 - q);
                    if (j & cb) j ^= tb;
                }
                tmp[u] = st[j];
            }
            __syncthreads();
#pragma unroll
            for (int u = 0; u < 4; u++)
                st[u * 1024 + tid] = tmp[u];
            __syncthreads();
        }
    }
    for (int i = tid; i < DIM; i += nt) g_psi0[i] = st[i];
}

// ---------------- Kernel B: per-sample layer-4 gates + f16 features ------
__global__ void k_states(const float* __restrict__ X,
                         const float* __restrict__ params) {
    __shared__ float2 st[DIM];
    int i = blockIdx.x, tid = threadIdx.x, nt = blockDim.x;
    for (int k = tid; k < DIM; k += nt) st[k] = g_psi0[k];
    __syncthreads();

    for (int q = 0; q < NQ; q++) {
        const float* p = params + ((NLAYERS - 1) * NQ + q) * 3;
        float2 T00, T01, T10, T11;
        make_UT(p[0], p[1], p[2], T00, T01, T10, T11);
        float x = X[i * NQ + q];
        float gc = cosf(0.5f * x), gs = sinf(0.5f * x);
        // V = G^T * T
        float2 V00 = make_float2(gc * T00.x + gs * T10.x, gc * T00.y + gs * T10.y);
        float2 V01 = make_float2(gc * T01.x + gs * T11.x, gc * T01.y + gs * T11.y);
        float2 V10 = make_float2(-gs * T00.x + gc * T10.x, -gs * T00.y + gc * T10.y);
        float2 V11 = make_float2(-gs * T01.x + gc * T11.x, -gs * T01.y + gc * T11.y);

        int mask = 1 << (NQ - 1 - q);
        for (int pi = tid; pi < DIM / 2; pi += nt) {
            int low = pi & (mask - 1);
            int hi  = (pi & ~(mask - 1)) << 1;
            int i0 = hi | low, i1 = i0 | mask;
            float2 s0 = st[i0], s1 = st[i1];
            st[i0] = cadd(cmul(V00, s0), cmul(V01, s1));
            st[i1] = cadd(cmul(V10, s0), cmul(V11, s1));
        }
        __syncthreads();
    }

    size_t rowoff = (size_t)i * DIM;
    for (int k = tid; k < DIM; k += nt) {
        float re = st[k].x, im = st[k].y;
        g_A0[rowoff + k] = __float2half_rn(re);
        g_A1[rowoff + k] = __float2half_rn(im);
        g_A2[rowoff + k] = __float2half_rn(re + im);
        g_A4[rowoff + k] = __float2half_rn(re - im);
    }
}

// =============  Kernel C: Gauss 3-mult f16 HMMA Gram  =====================
// k1 = <(a+b)_i, a_j>,  k2 = <a_i, (a+b)_j>,  k3 = <b_i, (a-b)_j>
// re = k1 - k3 ; im = k1 - k2 ; K_out = re^2 + im^2.
// 3 real GEMM chains at K=4096 (vs 2 at K=8192): 25% fewer MACs.
#define KROWB     8192                  // bytes per operand row (4096 f16)
#define NKT       64                    // 8192B / 128B chunks
#define TILE_B    16384                 // 128 rows x 128 bytes
#define STAGE_B   (6 * TILE_B)          // {A2,A0,A1}_i + {A0,A2,A4}_j = 96KB
#define NSTAGE    2
#define GRAM_SMEM (NSTAGE * STAGE_B)    // 192KB
#define GRAM_THREADS 256
#define NTILE (DIM / 128)               // 32
#define NBLK  (NTILE * (NTILE + 1) / 2) // 528

__device__ __forceinline__ uint32_t smem_u32(const void* p) {
    return (uint32_t)__cvta_generic_to_shared(p);
}
__device__ __forceinline__ void cp_async16(uint32_t dst, const void* src) {
    asm volatile("cp.async.cg.shared.global [%0], [%1], 16;" :: "r"(dst), "l"(src));
}
#define CP_COMMIT()  asm volatile("cp.async.commit_group;" ::: "memory")
#define CP_WAIT1()   asm volatile("cp.async.wait_group 1;" ::: "memory")
#define CP_WAIT0()   asm volatile("cp.async.wait_group 0;" ::: "memory")

__device__ __forceinline__ void ldsm4(uint32_t* r, uint32_t addr) {
    asm volatile("ldmatrix.sync.aligned.m8n8.x4.shared.b16 {%0,%1,%2,%3}, [%4];"
        : "=r"(r[0]), "=r"(r[1]), "=r"(r[2]), "=r"(r[3]) : "r"(addr));
}
__device__ __forceinline__ void mma_f16(float* c, const uint32_t* a,
                                        uint32_t b0, uint32_t b1) {
    asm volatile(
        "mma.sync.aligned.m16n8k16.row.col.f32.f16.f16.f32 "
        "{%0,%1,%2,%3}, {%4,%5,%6,%7}, {%8,%9}, {%0,%1,%2,%3};"
        : "+f"(c[0]), "+f"(c[1]), "+f"(c[2]), "+f"(c[3])
        : "r"(a[0]), "r"(a[1]), "r"(a[2]), "r"(a[3]), "r"(b0), "r"(b1));
}

__global__ void __launch_bounds__(GRAM_THREADS, 1)
k_gram_mma(float* __restrict__ K) {
    extern __shared__ __align__(1024) char smem[];
    const uint32_t smem_base = smem_u32(smem);
    const int tid  = threadIdx.x;
    const int wid  = tid >> 5;
    const int lane = tid & 31;
    const int wm = wid >> 2;            // 0..1  (64-row slab)
    const int wn = wid & 3;             // 0..3  (32-col slab)

    // triangular tile mapping (bi <= bj)
    int t = blockIdx.x;
    int bj = (int)((sqrtf(8.0f * (float)t + 1.0f) - 1.0f) * 0.5f);
    while ((bj + 1) * (bj + 2) / 2 <= t) bj++;
    while (bj * (bj + 1) / 2 > t) bj--;
    int bi = t - bj * (bj + 1) / 2;

    const char* gsrc[6];
    gsrc[0] = (const char*)g_A2 + (size_t)bi * 128 * KROWB;  // i: a+b
    gsrc[1] = (const char*)g_A0 + (size_t)bi * 128 * KROWB;  // i: a
    gsrc[2] = (const char*)g_A1 + (size_t)bi * 128 * KROWB;  // i: b
    gsrc[3] = (const char*)g_A0 + (size_t)bj * 128 * KROWB;  // j: a
    gsrc[4] = (const char*)g_A2 + (size_t)bj * 128 * KROWB;  // j: a+b
    gsrc[5] = (const char*)g_A4 + (size_t)bj * 128 * KROWB;  // j: a-b

    // ldmatrix per-thread geometry
    const int mat = lane >> 3, rl = lane & 7;
    const int rowA_base = wm * 64 + (mat & 1) * 8 + rl;   // + mt*16
    const uint32_t kselA = (uint32_t)((mat >> 1) * 16);
    const uint32_t xA = (uint32_t)(rowA_base & 7) << 4;
    const int rowB_base = wn * 32 + (mat >> 1) * 8 + rl;  // + np*16
    const uint32_t kselB = (uint32_t)((mat & 1) * 16);
    const uint32_t xB = (uint32_t)(rowB_base & 7) << 4;

    float acc1[4][4][4], acc2[4][4][4], acc3[4][4][4];
#pragma unroll
    for (int mt = 0; mt < 4; mt++)
#pragma unroll
        for (int nt = 0; nt < 4; nt++)
#pragma unroll
            for (int r = 0; r < 4; r++) {
                acc1[mt][nt][r] = 0.f; acc2[mt][nt][r] = 0.f; acc3[mt][nt][r] = 0.f;
            }

    // ---------------- prologue: fill 2 stages --------------------------
#pragma unroll 1
    for (int pk = 0; pk < NSTAGE; pk++) {
        uint32_t sb = smem_base + pk * STAGE_B;
#pragma unroll
        for (int tt = 0; tt < 6; tt++) {
#pragma unroll
            for (int u = 0; u < 4; u++) {
                int p = u * 256 + tid;
                int rr = p >> 3, cc = p & 7;
                uint32_t dst = sb + tt * TILE_B + (uint32_t)rr * 128 +
                               (((uint32_t)cc * 16) ^ (((uint32_t)rr & 7) << 4));
                cp_async16(dst, gsrc[tt] + (size_t)rr * KROWB + pk * 128 + cc * 16);
            }
        }
        CP_COMMIT();
    }

    // ---------------- main loop ----------------------------------------
#pragma unroll 1
    for (int kt = 0; kt < NKT; kt++) {
        CP_WAIT1();
        __syncthreads();

        uint32_t sb = smem_base + (kt & 1) * STAGE_B;
        uint32_t iA2 = sb              + (uint32_t)rowA_base * 128;
        uint32_t iA0 = sb + 1 * TILE_B + (uint32_t)rowA_base * 128;
        uint32_t iA1 = sb + 2 * TILE_B + (uint32_t)rowA_base * 128;
        uint32_t jA0 = sb + 3 * TILE_B + (uint32_t)rowB_base * 128;
        uint32_t jA2 = sb + 4 * TILE_B + (uint32_t)rowB_base * 128;
        uint32_t jA4 = sb + 5 * TILE_B + (uint32_t)rowB_base * 128;

#pragma unroll
        for (int ks = 0; ks < 4; ks++) {
            uint32_t cA = ((uint32_t)(ks * 32) + kselA) ^ xA;
            uint32_t cB = ((uint32_t)(ks * 32) + kselB) ^ xB;

            // chain 1: k1 = <(a+b)_i, a_j>  -> acc1
            {
                uint32_t af[4][4], bf[2][4];
#pragma unroll
                for (int mt = 0; mt < 4; mt++) ldsm4(af[mt], iA2 + mt * 2048 + cA);
#pragma unroll
                for (int np = 0; np < 2; np++) ldsm4(bf[np], jA0 + np * 2048 + cB);
#pragma unroll
                for (int mt = 0; mt < 4; mt++)
#pragma unroll
                    for (int np = 0; np < 2; np++)
#pragma unroll
                        for (int h = 0; h < 2; h++)
                            mma_f16(acc1[mt][np * 2 + h], af[mt],
                                    bf[np][h * 2], bf[np][h * 2 + 1]);
            }
            // chain 2: k2 = <a_i, (a+b)_j>  -> acc2
            {
                uint32_t af[4][4], bf[2][4];
#pragma unroll
                for (int mt = 0; mt < 4; mt++) ldsm4(af[mt], iA0 + mt * 2048 + cA);
#pragma unroll
                for (int np = 0; np < 2; np++) ldsm4(bf[np], jA2 + np * 2048 + cB);
#pragma unroll
                for (int mt = 0; mt < 4; mt++)
#pragma unroll
                    for (int np = 0; np < 2; np++)
#pragma unroll
                        for (int h = 0; h < 2; h++)
                            mma_f16(acc2[mt][np * 2 + h], af[mt],
                                    bf[np][h * 2], bf[np][h * 2 + 1]);
            }
            // chain 3: k3 = <b_i, (a-b)_j>  -> acc3
            {
                uint32_t af[4][4], bf[2][4];
#pragma unroll
                for (int mt = 0; mt < 4; mt++) ldsm4(af[mt], iA1 + mt * 2048 + cA);
#pragma unroll
                for (int np = 0; np < 2; np++) ldsm4(bf[np], jA4 + np * 2048 + cB);
#pragma unroll
                for (int mt = 0; mt < 4; mt++)
#pragma unroll
                    for (int np = 0; np < 2; np++)
#pragma unroll
                        for (int h = 0; h < 2; h++)
                            mma_f16(acc3[mt][np * 2 + h], af[mt],
                                    bf[np][h * 2], bf[np][h * 2 + 1]);
            }
        }

        __syncthreads();

        int nk = kt + NSTAGE;
        if (nk < NKT) {
#pragma unroll
            for (int tt = 0; tt < 6; tt++) {
#pragma unroll
                for (int u = 0; u < 4; u++) {
                    int p = u * 256 + tid;
                    int rr = p >> 3, cc = p & 7;
                    uint32_t dst = sb + tt * TILE_B + (uint32_t)rr * 128 +
                                   (((uint32_t)cc * 16) ^ (((uint32_t)rr & 7) << 4));
                    cp_async16(dst, gsrc[tt] + (size_t)rr * KROWB + nk * 128 + cc * 16);
                }
            }
        }
        CP_COMMIT();
    }

    // ------- epilogue: re = k1-k3, im = k1-k2, K = re^2 + im^2 ----------
    CP_WAIT0();
    __syncthreads();                      // smem tiles dead; reuse for transpose

    float* T = (float*)smem;              // [128 cols][132 pitch] local transpose
    const int r0 = bi * 128 + wm * 64 + (lane >> 2);
    const int c0 = bj * 128 + wn * 32 + (lane & 3) * 2;
    const int rl0 = wm * 64 + (lane >> 2);
    const int cl0 = wn * 32 + (lane & 3) * 2;
#pragma unroll
    for (int mt = 0; mt < 4; mt++) {
#pragma unroll
        for (int nt = 0; nt < 4; nt++) {
            int row = r0 + mt * 16;
            int col = c0 + nt * 8;
            float v[4];
#pragma unroll
            for (int r = 0; r < 4; r++) {
                float re = acc1[mt][nt][r] - acc3[mt][nt][r];
                float im = acc1[mt][nt][r] - acc2[mt][nt][r];
                v[r] = re * re + im * im;
            }
            *(float2*)(K + (size_t)row * BSZ + col)       = make_float2(v[0], v[1]);
            *(float2*)(K + (size_t)(row + 8) * BSZ + col) = make_float2(v[2], v[3]);
            if (bi != bj) {
                int rr = rl0 + mt * 16, cc = cl0 + nt * 8;
                T[cc * 132 + rr]           = v[0];
                T[(cc + 1) * 132 + rr]     = v[1];
                T[cc * 132 + rr + 8]       = v[2];
                T[(cc + 1) * 132 + rr + 8] = v[3];
            }
        }
    }
    __syncthreads();
    if (bi != bj) {
        // coalesced mirror: row c of T -> K[(bj*128+c)][bi*128 ..]
        int c = tid >> 1, half = tid & 1;
        float4* dst = (float4*)(K + (size_t)(bj * 128 + c) * BSZ + bi * 128 + half * 64);
        const float* src = T + c * 132 + half * 64;
#pragma unroll
        for (int i = 0; i < 16; i++)
            dst[i] = make_float4(src[4 * i], src[4 * i + 1],
                                 src[4 * i + 2], src[4 * i + 3]);
    }
}

// -------------------------------------------------------------------------
extern "C" void kernel_launch(void* const* d_in, const int* in_sizes, int n_in,
                              void* d_out, int out_size) {
    const float* X      = (const float*)d_in[0];   // (4096, 12)
    const float* params = (const float*)d_in[1];   // (5, 12, 3)
    float* K = (float*)d_out;                      // (4096, 4096)

    cudaFuncSetAttribute(k_gram_mma, cudaFuncAttributeMaxDynamicSharedMemorySize,
                         GRAM_SMEM);

    k_psi0    <<<1,    1024>>>(params);
    k_states  <<<BSZ,  256>>>(X, params);
    k_gram_mma<<<NBLK, GRAM_THREADS, GRAM_SMEM>>>(K);
}